// round 1
// baseline (speedup 1.0000x reference)
#include <cuda_runtime.h>
#include <math.h>

// Problem dims
#define BB 2
#define SS 2048
#define DD 1024
#define HH 16
#define DK 64
#define MROWS (BB * SS)   // 4096
#define BHT (BB * HH)     // 32
#define NQT (SS / 64)     // 32 tiles of 64

// -------- scratch (static __device__ globals; no allocation allowed) --------
__device__ float g_Q[(size_t)BB * SS * DD];                 // 16 MB
__device__ float g_K[(size_t)BB * SS * DD];                 // 16 MB (also V: reference bug v = k)
__device__ float g_C[(size_t)BB * SS * DD];                 // 16 MB concat
__device__ float g_P[(size_t)BB * HH * SS * SS];            // 512 MB attn probs

// ============================================================================
// Generic C = A @ W^T + bias  (A:[M,K] rm, W:[N,K] rm), 128x128x8 tiles, 8x8/thread
// ============================================================================
__global__ __launch_bounds__(256) void sgemm_abT_bias(
    const float* __restrict__ A, const float* __restrict__ W,
    const float* __restrict__ bias, float* __restrict__ Y,
    int M, int N, int K)
{
    __shared__ float As[8][128];
    __shared__ float Bs[8][128];

    const int tid = threadIdx.x;
    const int tx = tid & 15;
    const int ty = tid >> 4;
    const int m0 = blockIdx.y * 128;
    const int n0 = blockIdx.x * 128;

    const int lr = tid >> 1;          // 0..127
    const int lc = (tid & 1) * 4;     // 0 or 4

    const float* Aptr = A + (size_t)(m0 + lr) * K + lc;
    const float* Wptr = W + (size_t)(n0 + lr) * K + lc;

    float acc[8][8];
#pragma unroll
    for (int i = 0; i < 8; i++)
#pragma unroll
        for (int j = 0; j < 8; j++) acc[i][j] = 0.f;

    for (int k0 = 0; k0 < K; k0 += 8) {
        float4 av = *(const float4*)(Aptr + k0);
        float4 bv = *(const float4*)(Wptr + k0);
        As[lc + 0][lr] = av.x; As[lc + 1][lr] = av.y;
        As[lc + 2][lr] = av.z; As[lc + 3][lr] = av.w;
        Bs[lc + 0][lr] = bv.x; Bs[lc + 1][lr] = bv.y;
        Bs[lc + 2][lr] = bv.z; Bs[lc + 3][lr] = bv.w;
        __syncthreads();

#pragma unroll
        for (int kk = 0; kk < 8; kk++) {
            float a[8], b[8];
#pragma unroll
            for (int i = 0; i < 8; i++) a[i] = As[kk][ty * 8 + i];
#pragma unroll
            for (int j = 0; j < 8; j++) b[j] = Bs[kk][tx * 8 + j];
#pragma unroll
            for (int i = 0; i < 8; i++)
#pragma unroll
                for (int j = 0; j < 8; j++) acc[i][j] += a[i] * b[j];
        }
        __syncthreads();
    }

#pragma unroll
    for (int i = 0; i < 8; i++) {
        const int m = m0 + ty * 8 + i;
        float* yrow = Y + (size_t)m * N + n0 + tx * 8;
        const float* brow = bias + n0 + tx * 8;
#pragma unroll
        for (int j = 0; j < 8; j++) yrow[j] = acc[i][j] + brow[j];
    }
}

// ============================================================================
// scores: P[bh,q,k] = (Q_h[q,:] . K_h[k,:]) * 1/8, causal tiles only (kt<=qt)
// 64x64 output tile, inner dim 64, 256 threads, 4x4 per thread
// ============================================================================
__global__ __launch_bounds__(256) void scores_kernel(void)
{
    const int kt = blockIdx.x;
    const int qt = blockIdx.y;
    if (kt > qt) return;
    const int bh = blockIdx.z;
    const int b = bh >> 4;        // /HH
    const int h = bh & 15;

    __shared__ float Qs[64][65];
    __shared__ float Ks[64][65];

    const int tid = threadIdx.x;
    {
        const int r  = tid >> 2;            // 0..63
        const int c0 = (tid & 3) * 16;      // 0,16,32,48
        const float* qrow = g_Q + ((size_t)b * SS + qt * 64 + r) * DD + h * DK;
        const float* krow = g_K + ((size_t)b * SS + kt * 64 + r) * DD + h * DK;
#pragma unroll
        for (int u = 0; u < 16; u += 4) {
            float4 v = *(const float4*)(qrow + c0 + u);
            Qs[r][c0 + u + 0] = v.x; Qs[r][c0 + u + 1] = v.y;
            Qs[r][c0 + u + 2] = v.z; Qs[r][c0 + u + 3] = v.w;
            float4 w = *(const float4*)(krow + c0 + u);
            Ks[r][c0 + u + 0] = w.x; Ks[r][c0 + u + 1] = w.y;
            Ks[r][c0 + u + 2] = w.z; Ks[r][c0 + u + 3] = w.w;
        }
    }
    __syncthreads();

    const int tx = tid & 15;
    const int ty = tid >> 4;
    float acc[4][4];
#pragma unroll
    for (int i = 0; i < 4; i++)
#pragma unroll
        for (int j = 0; j < 4; j++) acc[i][j] = 0.f;

#pragma unroll 8
    for (int d = 0; d < 64; d++) {
        float qf[4], kf[4];
#pragma unroll
        for (int i = 0; i < 4; i++) qf[i] = Qs[ty * 4 + i][d];
#pragma unroll
        for (int j = 0; j < 4; j++) kf[j] = Ks[tx * 4 + j][d];
#pragma unroll
        for (int i = 0; i < 4; i++)
#pragma unroll
            for (int j = 0; j < 4; j++) acc[i][j] += qf[i] * kf[j];
    }

    const float scale = 0.125f;   // 1/sqrt(64)
#pragma unroll
    for (int i = 0; i < 4; i++) {
        float* prow = g_P + ((size_t)bh * SS + qt * 64 + ty * 4 + i) * SS + kt * 64 + tx * 4;
#pragma unroll
        for (int j = 0; j < 4; j++) prow[j] = acc[i][j] * scale;
    }
}

// ============================================================================
// softmax per row (causal), row cached in smem: 1 global read + 1 write
// ============================================================================
__global__ __launch_bounds__(256) void softmax_kernel(void)
{
    const int row = blockIdx.x;            // 0 .. B*H*S-1
    const int q = row & (SS - 1);
    const int len = q + 1;

    __shared__ float buf[SS];
    __shared__ float red[8];
    __shared__ float s_bcast;

    float* Prow = g_P + (size_t)row * SS;
    const int tid = threadIdx.x;
    const int lane = tid & 31, warp = tid >> 5;

    float m = -INFINITY;
    for (int k = tid; k < len; k += 256) {
        float v = Prow[k];
        buf[k] = v;
        m = fmaxf(m, v);
    }
#pragma unroll
    for (int o = 16; o; o >>= 1) m = fmaxf(m, __shfl_xor_sync(0xFFFFFFFFu, m, o));
    if (lane == 0) red[warp] = m;
    __syncthreads();
    if (tid == 0) {
        float t = red[0];
#pragma unroll
        for (int i = 1; i < 8; i++) t = fmaxf(t, red[i]);
        s_bcast = t;
    }
    __syncthreads();
    const float rowmax = s_bcast;
    __syncthreads();

    float s = 0.f;
    for (int k = tid; k < len; k += 256) {
        float e = __expf(buf[k] - rowmax);
        buf[k] = e;
        s += e;
    }
#pragma unroll
    for (int o = 16; o; o >>= 1) s += __shfl_xor_sync(0xFFFFFFFFu, s, o);
    if (lane == 0) red[warp] = s;
    __syncthreads();
    if (tid == 0) {
        float t = 0.f;
#pragma unroll
        for (int i = 0; i < 8; i++) t += red[i];
        s_bcast = t;
    }
    __syncthreads();
    const float inv = 1.0f / s_bcast;

    for (int k = tid; k < SS; k += 256)
        Prow[k] = (k < len) ? buf[k] * inv : 0.f;
}

// ============================================================================
// AW[b,q,k] = sum_h P[b,h,q,k]   (float4 per thread)
// ============================================================================
__global__ __launch_bounds__(256) void aw_kernel(float* __restrict__ AW)
{
    const size_t idx = (size_t)blockIdx.x * 256 + threadIdx.x;   // over B*S*S/4
    const size_t k4 = (idx % (SS / 4)) * 4;
    const size_t q = (idx / (SS / 4)) % SS;
    const size_t b = idx / ((size_t)(SS / 4) * SS);

    float4 s = make_float4(0.f, 0.f, 0.f, 0.f);
#pragma unroll
    for (int h = 0; h < HH; h++) {
        const float4 v = *(const float4*)(g_P + (((size_t)(b * HH + h) * SS + q) * SS + k4));
        s.x += v.x; s.y += v.y; s.z += v.z; s.w += v.w;
    }
    *(float4*)(AW + ((size_t)b * SS + q) * SS + k4) = s;
}

// ============================================================================
// C[b,q, h*64+d] = sum_k P[bh,q,k] * V[b,k,h*64+d]   (V = g_K), causal k-tiles
// ============================================================================
__global__ __launch_bounds__(256) void pv_kernel(void)
{
    const int qt = blockIdx.x;
    const int bh = blockIdx.y;
    const int b = bh >> 4;
    const int h = bh & 15;

    __shared__ float Ps[64][65];
    __shared__ float Vs[64][65];

    const int tid = threadIdx.x;
    const int tx = tid & 15;
    const int ty = tid >> 4;
    const int r  = tid >> 2;
    const int c0 = (tid & 3) * 16;

    float acc[4][4];
#pragma unroll
    for (int i = 0; i < 4; i++)
#pragma unroll
        for (int j = 0; j < 4; j++) acc[i][j] = 0.f;

    for (int kt = 0; kt <= qt; kt++) {
        const float* prow = g_P + ((size_t)bh * SS + qt * 64 + r) * SS + kt * 64;
        const float* vrow = g_K + ((size_t)b * SS + kt * 64 + r) * DD + h * DK;
#pragma unroll
        for (int u = 0; u < 16; u += 4) {
            float4 v = *(const float4*)(prow + c0 + u);
            Ps[r][c0 + u + 0] = v.x; Ps[r][c0 + u + 1] = v.y;
            Ps[r][c0 + u + 2] = v.z; Ps[r][c0 + u + 3] = v.w;
            float4 w = *(const float4*)(vrow + c0 + u);
            Vs[r][c0 + u + 0] = w.x; Vs[r][c0 + u + 1] = w.y;
            Vs[r][c0 + u + 2] = w.z; Vs[r][c0 + u + 3] = w.w;
        }
        __syncthreads();

#pragma unroll 8
        for (int kk = 0; kk < 64; kk++) {
            float pf[4], vf[4];
#pragma unroll
            for (int i = 0; i < 4; i++) pf[i] = Ps[ty * 4 + i][kk];
#pragma unroll
            for (int j = 0; j < 4; j++) vf[j] = Vs[kk][tx * 4 + j];
#pragma unroll
            for (int i = 0; i < 4; i++)
#pragma unroll
                for (int j = 0; j < 4; j++) acc[i][j] += pf[i] * vf[j];
        }
        __syncthreads();
    }

#pragma unroll
    for (int i = 0; i < 4; i++) {
        float* crow = g_C + ((size_t)b * SS + qt * 64 + ty * 4 + i) * DD + h * DK + tx * 4;
#pragma unroll
        for (int j = 0; j < 4; j++) crow[j] = acc[i][j];
    }
}

// ============================================================================
// launch
// ============================================================================
extern "C" void kernel_launch(void* const* d_in, const int* in_sizes, int n_in,
                              void* d_out, int out_size)
{
    const float* x    = (const float*)d_in[0];
    const float* z    = (const float*)d_in[1];
    // d_in[2] = mask (causal tril; handled analytically)
    const float* wq_w = (const float*)d_in[3];
    const float* wq_b = (const float*)d_in[4];
    const float* wk_w = (const float*)d_in[5];
    const float* wk_b = (const float*)d_in[6];
    // d_in[7], d_in[8] = wv (dead param in reference: v uses wk)
    const float* wo_w = (const float*)d_in[9];
    const float* wo_b = (const float*)d_in[10];

    float* out = (float*)d_out;                              // [B,S,D]
    float* AW  = out + (size_t)BB * SS * DD;                 // [B,S,S]

    float *pQ, *pK, *pC;
    cudaGetSymbolAddress((void**)&pQ, g_Q);
    cudaGetSymbolAddress((void**)&pK, g_K);
    cudaGetSymbolAddress((void**)&pC, g_C);

    const dim3 gProj(DD / 128, MROWS / 128);                 // (8,32)
    sgemm_abT_bias<<<gProj, 256>>>(x, wq_w, wq_b, pQ, MROWS, DD, DD);
    sgemm_abT_bias<<<gProj, 256>>>(z, wk_w, wk_b, pK, MROWS, DD, DD);

    scores_kernel<<<dim3(NQT, NQT, BHT), 256>>>();

    softmax_kernel<<<BHT * SS, 256>>>();

    aw_kernel<<<(BB * SS * (SS / 4)) / 256, 256>>>(AW);

    pv_kernel<<<dim3(NQT, BHT), 256>>>();

    sgemm_abT_bias<<<gProj, 256>>>(pC, wo_w, wo_b, out, MROWS, DD, DD);
}

// round 4
// speedup vs baseline: 1.1884x; 1.1884x over previous
#include <cuda_runtime.h>
#include <cuda_bf16.h>
#include <cstdint>
#include <math.h>

// Problem dims
#define BB 2
#define SS 2048
#define DD 1024
#define HH 16
#define DK 64
#define MROWS (BB * SS)   // 4096
#define BHT (BB * HH)     // 32
#define NQT (SS / 64)     // 32 tiles of 64

// -------- scratch (static __device__ globals; no allocation allowed) --------
__device__ float g_Q[(size_t)BB * SS * DD];                 // 16 MB
__device__ float g_K[(size_t)BB * SS * DD];                 // 16 MB (also V: reference bug v = k)
__device__ float g_C[(size_t)BB * SS * DD];                 // 16 MB concat
__device__ float g_P[(size_t)BB * HH * SS * SS];            // 512 MB attn probs

// ============================================================================
// mma.sync bf16 GEMM: Y[M,N] = A[M,K] @ W[N,K]^T + bias  (bf16x3 compensation)
// 512 threads / 16 warps, CTA tile 128x128, warp tile 32x32, K-chunk 64
// smem: Ah | Al | Wh | Wl, each 128 rows x 80 bf16 pitch (data cols 0..63)
// ============================================================================
#define GPITCH 80
#define MAT_BYTES (128 * GPITCH * 2)          // 20480
#define GEMM_SMEM (4 * MAT_BYTES)             // 81920

__device__ __forceinline__ uint32_t pack_bf16(__nv_bfloat16 a, __nv_bfloat16 b) {
    return (uint32_t)__bfloat16_as_ushort(a) | ((uint32_t)__bfloat16_as_ushort(b) << 16);
}

__device__ __forceinline__ void cvt_store4(__nv_bfloat16* H, __nv_bfloat16* L,
                                           int idx, float4 v) {
    __nv_bfloat16 h0 = __float2bfloat16_rn(v.x);
    __nv_bfloat16 h1 = __float2bfloat16_rn(v.y);
    __nv_bfloat16 h2 = __float2bfloat16_rn(v.z);
    __nv_bfloat16 h3 = __float2bfloat16_rn(v.w);
    __nv_bfloat16 l0 = __float2bfloat16_rn(v.x - __bfloat162float(h0));
    __nv_bfloat16 l1 = __float2bfloat16_rn(v.y - __bfloat162float(h1));
    __nv_bfloat16 l2 = __float2bfloat16_rn(v.z - __bfloat162float(h2));
    __nv_bfloat16 l3 = __float2bfloat16_rn(v.w - __bfloat162float(h3));
    *(uint32_t*)(H + idx)     = pack_bf16(h0, h1);
    *(uint32_t*)(H + idx + 2) = pack_bf16(h2, h3);
    *(uint32_t*)(L + idx)     = pack_bf16(l0, l1);
    *(uint32_t*)(L + idx + 2) = pack_bf16(l2, l3);
}

#define MMA_BF16(C, A0, A1, A2, A3, B0, B1) \
    asm volatile( \
        "mma.sync.aligned.m16n8k16.row.col.f32.bf16.bf16.f32 " \
        "{%0,%1,%2,%3}, {%4,%5,%6,%7}, {%8,%9}, {%0,%1,%2,%3};" \
        : "+f"((C)[0]), "+f"((C)[1]), "+f"((C)[2]), "+f"((C)[3]) \
        : "r"(A0), "r"(A1), "r"(A2), "r"(A3), "r"(B0), "r"(B1))

__global__ void __launch_bounds__(512, 1) gemm_mma(
    const float* __restrict__ A, const float* __restrict__ W,
    const float* __restrict__ bias, float* __restrict__ Y,
    int K, int N)
{
    extern __shared__ char sm[];
    __nv_bfloat16* Ah = (__nv_bfloat16*)(sm);
    __nv_bfloat16* Al = (__nv_bfloat16*)(sm + MAT_BYTES);
    __nv_bfloat16* Wh = (__nv_bfloat16*)(sm + 2 * MAT_BYTES);
    __nv_bfloat16* Wl = (__nv_bfloat16*)(sm + 3 * MAT_BYTES);

    const int tid = threadIdx.x;
    const int lane = tid & 31;
    const int wid = tid >> 5;
    const int wy = wid >> 2;            // 0..3
    const int wx = wid & 3;             // 0..3
    const int m0 = blockIdx.y * 128;
    const int n0 = blockIdx.x * 128;

    // staging map: thread -> (row, 16 consecutive k)
    const int srow = tid >> 2;          // 0..127
    const int sk0 = (tid & 3) << 4;     // 0,16,32,48
    const float* aptr = A + (size_t)(m0 + srow) * K + sk0;
    const float* wptr = W + (size_t)(n0 + srow) * K + sk0;
    const int sidx = srow * GPITCH + sk0;

    float acc[2][4][4];
#pragma unroll
    for (int t = 0; t < 2; t++)
#pragma unroll
        for (int u = 0; u < 4; u++)
#pragma unroll
            for (int i = 0; i < 4; i++) acc[t][u][i] = 0.f;

    // fragment smem base offsets (bf16 units)
    const int r8 = lane >> 2;           // 0..7
    const int q2 = (lane & 3) << 1;     // 0,2,4,6

    const int nchunk = K >> 6;
    for (int c = 0; c < nchunk; c++) {
        const int kc = c << 6;
        float4 va[4], vw[4];
#pragma unroll
        for (int i = 0; i < 4; i++) {
            va[i] = *(const float4*)(aptr + kc + i * 4);
            vw[i] = *(const float4*)(wptr + kc + i * 4);
        }
        __syncthreads();                // previous chunk's compute done reading smem
#pragma unroll
        for (int i = 0; i < 4; i++) {
            cvt_store4(Ah, Al, sidx + i * 4, va[i]);
            cvt_store4(Wh, Wl, sidx + i * 4, vw[i]);
        }
        __syncthreads();

#pragma unroll
        for (int ks = 0; ks < 4; ks++) {
            const int kk = ks << 4;
            uint32_t ah[2][4], al[2][4];
#pragma unroll
            for (int t = 0; t < 2; t++) {
                const int base = (wy * 32 + t * 16 + r8) * GPITCH + q2 + kk;
                ah[t][0] = *(const uint32_t*)(Ah + base);
                ah[t][1] = *(const uint32_t*)(Ah + base + 8 * GPITCH);
                ah[t][2] = *(const uint32_t*)(Ah + base + 8);
                ah[t][3] = *(const uint32_t*)(Ah + base + 8 * GPITCH + 8);
                al[t][0] = *(const uint32_t*)(Al + base);
                al[t][1] = *(const uint32_t*)(Al + base + 8 * GPITCH);
                al[t][2] = *(const uint32_t*)(Al + base + 8);
                al[t][3] = *(const uint32_t*)(Al + base + 8 * GPITCH + 8);
            }
#pragma unroll
            for (int u = 0; u < 4; u++) {
                const int nb = (wx * 32 + u * 8 + r8) * GPITCH + q2 + kk;
                const uint32_t bh0 = *(const uint32_t*)(Wh + nb);
                const uint32_t bh1 = *(const uint32_t*)(Wh + nb + 8);
                const uint32_t bl0 = *(const uint32_t*)(Wl + nb);
                const uint32_t bl1 = *(const uint32_t*)(Wl + nb + 8);
#pragma unroll
                for (int t = 0; t < 2; t++) {
                    MMA_BF16(acc[t][u], ah[t][0], ah[t][1], ah[t][2], ah[t][3], bh0, bh1);
                    MMA_BF16(acc[t][u], ah[t][0], ah[t][1], ah[t][2], ah[t][3], bl0, bl1);
                    MMA_BF16(acc[t][u], al[t][0], al[t][1], al[t][2], al[t][3], bh0, bh1);
                }
            }
        }
    }

    // epilogue: c0,c1 -> (row, col..col+1); c2,c3 -> (row+8, ...)
#pragma unroll
    for (int t = 0; t < 2; t++) {
        const int r0 = m0 + wy * 32 + t * 16 + r8;
#pragma unroll
        for (int u = 0; u < 4; u++) {
            const int col = n0 + wx * 32 + u * 8 + q2;
            const float b0 = bias[col], b1 = bias[col + 1];
            float2 v0, v1;
            v0.x = acc[t][u][0] + b0; v0.y = acc[t][u][1] + b1;
            v1.x = acc[t][u][2] + b0; v1.y = acc[t][u][3] + b1;
            *(float2*)(Y + (size_t)r0 * N + col) = v0;
            *(float2*)(Y + (size_t)(r0 + 8) * N + col) = v1;
        }
    }
}

// ============================================================================
// scores: P[bh,q,k] = (Q_h[q,:] . K_h[k,:]) * 1/8, causal tiles only (kt<=qt)
// ============================================================================
__global__ __launch_bounds__(256) void scores_kernel(void)
{
    const int kt = blockIdx.x;
    const int qt = blockIdx.y;
    if (kt > qt) return;
    const int bh = blockIdx.z;
    const int b = bh >> 4;
    const int h = bh & 15;

    __shared__ float Qs[64][65];
    __shared__ float Ks[64][65];

    const int tid = threadIdx.x;
    {
        const int r  = tid >> 2;
        const int c0 = (tid & 3) * 16;
        const float* qrow = g_Q + ((size_t)b * SS + qt * 64 + r) * DD + h * DK;
        const float* krow = g_K + ((size_t)b * SS + kt * 64 + r) * DD + h * DK;
#pragma unroll
        for (int u = 0; u < 16; u += 4) {
            float4 v = *(const float4*)(qrow + c0 + u);
            Qs[r][c0 + u + 0] = v.x; Qs[r][c0 + u + 1] = v.y;
            Qs[r][c0 + u + 2] = v.z; Qs[r][c0 + u + 3] = v.w;
            float4 w = *(const float4*)(krow + c0 + u);
            Ks[r][c0 + u + 0] = w.x; Ks[r][c0 + u + 1] = w.y;
            Ks[r][c0 + u + 2] = w.z; Ks[r][c0 + u + 3] = w.w;
        }
    }
    __syncthreads();

    const int tx = tid & 15;
    const int ty = tid >> 4;
    float acc[4][4];
#pragma unroll
    for (int i = 0; i < 4; i++)
#pragma unroll
        for (int j = 0; j < 4; j++) acc[i][j] = 0.f;

#pragma unroll 8
    for (int d = 0; d < 64; d++) {
        float qf[4], kf[4];
#pragma unroll
        for (int i = 0; i < 4; i++) qf[i] = Qs[ty * 4 + i][d];
#pragma unroll
        for (int j = 0; j < 4; j++) kf[j] = Ks[tx * 4 + j][d];
#pragma unroll
        for (int i = 0; i < 4; i++)
#pragma unroll
            for (int j = 0; j < 4; j++) acc[i][j] += qf[i] * kf[j];
    }

    const float scale = 0.125f;
#pragma unroll
    for (int i = 0; i < 4; i++) {
        float* prow = g_P + ((size_t)bh * SS + qt * 64 + ty * 4 + i) * SS + kt * 64 + tx * 4;
#pragma unroll
        for (int j = 0; j < 4; j++) prow[j] = acc[i][j] * scale;
    }
}

// ============================================================================
// softmax per row (causal), row cached in smem
// ============================================================================
__global__ __launch_bounds__(256) void softmax_kernel(void)
{
    const int row = blockIdx.x;
    const int q = row & (SS - 1);
    const int len = q + 1;

    __shared__ float buf[SS];
    __shared__ float red[8];
    __shared__ float s_bcast;

    float* Prow = g_P + (size_t)row * SS;
    const int tid = threadIdx.x;
    const int lane = tid & 31, warp = tid >> 5;

    float m = -INFINITY;
    for (int k = tid; k < len; k += 256) {
        float v = Prow[k];
        buf[k] = v;
        m = fmaxf(m, v);
    }
#pragma unroll
    for (int o = 16; o; o >>= 1) m = fmaxf(m, __shfl_xor_sync(0xFFFFFFFFu, m, o));
    if (lane == 0) red[warp] = m;
    __syncthreads();
    if (tid == 0) {
        float t = red[0];
#pragma unroll
        for (int i = 1; i < 8; i++) t = fmaxf(t, red[i]);
        s_bcast = t;
    }
    __syncthreads();
    const float rowmax = s_bcast;
    __syncthreads();

    float s = 0.f;
    for (int k = tid; k < len; k += 256) {
        float e = __expf(buf[k] - rowmax);
        buf[k] = e;
        s += e;
    }
#pragma unroll
    for (int o = 16; o; o >>= 1) s += __shfl_xor_sync(0xFFFFFFFFu, s, o);
    if (lane == 0) red[warp] = s;
    __syncthreads();
    if (tid == 0) {
        float t = 0.f;
#pragma unroll
        for (int i = 0; i < 8; i++) t += red[i];
        s_bcast = t;
    }
    __syncthreads();
    const float inv = 1.0f / s_bcast;

    for (int k = tid; k < SS; k += 256)
        Prow[k] = (k < len) ? buf[k] * inv : 0.f;
}

// ============================================================================
// AW[b,q,k] = sum_h P[b,h,q,k]
// ============================================================================
__global__ __launch_bounds__(256) void aw_kernel(float* __restrict__ AW)
{
    const size_t idx = (size_t)blockIdx.x * 256 + threadIdx.x;
    const size_t k4 = (idx % (SS / 4)) * 4;
    const size_t q = (idx / (SS / 4)) % SS;
    const size_t b = idx / ((size_t)(SS / 4) * SS);

    float4 s = make_float4(0.f, 0.f, 0.f, 0.f);
#pragma unroll
    for (int h = 0; h < HH; h++) {
        const float4 v = *(const float4*)(g_P + (((size_t)(b * HH + h) * SS + q) * SS + k4));
        s.x += v.x; s.y += v.y; s.z += v.z; s.w += v.w;
    }
    *(float4*)(AW + ((size_t)b * SS + q) * SS + k4) = s;
}

// ============================================================================
// C[b,q, h*64+d] = sum_k P[bh,q,k] * V[b,k,h*64+d]   (V = g_K), causal k-tiles
// ============================================================================
__global__ __launch_bounds__(256) void pv_kernel(void)
{
    const int qt = blockIdx.x;
    const int bh = blockIdx.y;
    const int b = bh >> 4;
    const int h = bh & 15;

    __shared__ float Ps[64][65];
    __shared__ float Vs[64][65];

    const int tid = threadIdx.x;
    const int tx = tid & 15;
    const int ty = tid >> 4;
    const int r  = tid >> 2;
    const int c0 = (tid & 3) * 16;

    float acc[4][4];
#pragma unroll
    for (int i = 0; i < 4; i++)
#pragma unroll
        for (int j = 0; j < 4; j++) acc[i][j] = 0.f;

    for (int kt = 0; kt <= qt; kt++) {
        const float* prow = g_P + ((size_t)bh * SS + qt * 64 + r) * SS + kt * 64;
        const float* vrow = g_K + ((size_t)b * SS + kt * 64 + r) * DD + h * DK;
#pragma unroll
        for (int u = 0; u < 16; u += 4) {
            float4 v = *(const float4*)(prow + c0 + u);
            Ps[r][c0 + u + 0] = v.x; Ps[r][c0 + u + 1] = v.y;
            Ps[r][c0 + u + 2] = v.z; Ps[r][c0 + u + 3] = v.w;
            float4 w = *(const float4*)(vrow + c0 + u);
            Vs[r][c0 + u + 0] = w.x; Vs[r][c0 + u + 1] = w.y;
            Vs[r][c0 + u + 2] = w.z; Vs[r][c0 + u + 3] = w.w;
        }
        __syncthreads();

#pragma unroll 8
        for (int kk = 0; kk < 64; kk++) {
            float pf[4], vf[4];
#pragma unroll
            for (int i = 0; i < 4; i++) pf[i] = Ps[ty * 4 + i][kk];
#pragma unroll
            for (int j = 0; j < 4; j++) vf[j] = Vs[kk][tx * 4 + j];
#pragma unroll
            for (int i = 0; i < 4; i++)
#pragma unroll
                for (int j = 0; j < 4; j++) acc[i][j] += pf[i] * vf[j];
        }
        __syncthreads();
    }

#pragma unroll
    for (int i = 0; i < 4; i++) {
        float* crow = g_C + ((size_t)b * SS + qt * 64 + ty * 4 + i) * DD + h * DK + tx * 4;
#pragma unroll
        for (int j = 0; j < 4; j++) crow[j] = acc[i][j];
    }
}

// ============================================================================
// launch
// ============================================================================
extern "C" void kernel_launch(void* const* d_in, const int* in_sizes, int n_in,
                              void* d_out, int out_size)
{
    const float* x    = (const float*)d_in[0];
    const float* z    = (const float*)d_in[1];
    // d_in[2] = mask (causal tril; handled analytically)
    const float* wq_w = (const float*)d_in[3];
    const float* wq_b = (const float*)d_in[4];
    const float* wk_w = (const float*)d_in[5];
    const float* wk_b = (const float*)d_in[6];
    // d_in[7], d_in[8] = wv (dead param in reference: v uses wk)
    const float* wo_w = (const float*)d_in[9];
    const float* wo_b = (const float*)d_in[10];

    float* out = (float*)d_out;                              // [B,S,D]
    float* AW  = out + (size_t)BB * SS * DD;                 // [B,S,S]

    float *pQ, *pK, *pC;
    cudaGetSymbolAddress((void**)&pQ, g_Q);
    cudaGetSymbolAddress((void**)&pK, g_K);
    cudaGetSymbolAddress((void**)&pC, g_C);

    static int smem_set = 0;
    if (!smem_set) {
        cudaFuncSetAttribute(gemm_mma, cudaFuncAttributeMaxDynamicSharedMemorySize, GEMM_SMEM);
        smem_set = 1;
    }

    const dim3 gProj(DD / 128, MROWS / 128);                 // (8,32)
    gemm_mma<<<gProj, 512, GEMM_SMEM>>>(x, wq_w, wq_b, pQ, DD, DD);
    gemm_mma<<<gProj, 512, GEMM_SMEM>>>(z, wk_w, wk_b, pK, DD, DD);

    scores_kernel<<<dim3(NQT, NQT, BHT), 256>>>();

    softmax_kernel<<<BHT * SS, 256>>>();

    aw_kernel<<<(BB * SS * (SS / 4)) / 256, 256>>>(AW);

    pv_kernel<<<dim3(NQT, BHT), 256>>>();

    gemm_mma<<<gProj, 512, GEMM_SMEM>>>(pC, wo_w, wo_b, out, DD, DD);
}

// round 5
// speedup vs baseline: 1.7161x; 1.4441x over previous
#include <cuda_runtime.h>
#include <cuda_bf16.h>
#include <cstdint>
#include <math.h>

// Problem dims
#define BB 2
#define SS 2048
#define DD 1024
#define HH 16
#define DK 64
#define MROWS (BB * SS)   // 4096
#define BHT (BB * HH)     // 32

// -------- scratch (static __device__ globals; no allocation allowed) --------
__device__ float g_Q[(size_t)BB * SS * DD];                 // 16 MB
__device__ float g_K[(size_t)BB * SS * DD];                 // 16 MB (also V: reference bug v = k)
__device__ float g_C[(size_t)BB * SS * DD];                 // 16 MB concat
__device__ float g_P[(size_t)BB * HH * SS * SS];            // 512 MB attn probs

// ============================================================================
// common bf16 helpers
// ============================================================================
__device__ __forceinline__ uint32_t pack_bf16(__nv_bfloat16 a, __nv_bfloat16 b) {
    return (uint32_t)__bfloat16_as_ushort(a) | ((uint32_t)__bfloat16_as_ushort(b) << 16);
}

__device__ __forceinline__ void cvt_store4(__nv_bfloat16* H, __nv_bfloat16* L,
                                           int idx, float4 v) {
    __nv_bfloat16 h0 = __float2bfloat16_rn(v.x);
    __nv_bfloat16 h1 = __float2bfloat16_rn(v.y);
    __nv_bfloat16 h2 = __float2bfloat16_rn(v.z);
    __nv_bfloat16 h3 = __float2bfloat16_rn(v.w);
    __nv_bfloat16 l0 = __float2bfloat16_rn(v.x - __bfloat162float(h0));
    __nv_bfloat16 l1 = __float2bfloat16_rn(v.y - __bfloat162float(h1));
    __nv_bfloat16 l2 = __float2bfloat16_rn(v.z - __bfloat162float(h2));
    __nv_bfloat16 l3 = __float2bfloat16_rn(v.w - __bfloat162float(h3));
    *(uint32_t*)(H + idx)     = pack_bf16(h0, h1);
    *(uint32_t*)(H + idx + 2) = pack_bf16(h2, h3);
    *(uint32_t*)(L + idx)     = pack_bf16(l0, l1);
    *(uint32_t*)(L + idx + 2) = pack_bf16(l2, l3);
}

#define MMA_BF16(C, A0, A1, A2, A3, B0, B1) \
    asm volatile( \
        "mma.sync.aligned.m16n8k16.row.col.f32.bf16.bf16.f32 " \
        "{%0,%1,%2,%3}, {%4,%5,%6,%7}, {%8,%9}, {%0,%1,%2,%3};" \
        : "+f"((C)[0]), "+f"((C)[1]), "+f"((C)[2]), "+f"((C)[3]) \
        : "r"(A0), "r"(A1), "r"(A2), "r"(A3), "r"(B0), "r"(B1))

// ============================================================================
// mma.sync bf16 GEMM: Y[M,N] = A[M,K] @ W[N,K]^T + bias  (bf16x3 compensation)
// 512 threads / 16 warps, CTA tile 128x128, warp tile 32x32, K-chunk 64
// ============================================================================
#define GPITCH 80
#define MAT_BYTES (128 * GPITCH * 2)          // 20480
#define GEMM_SMEM (4 * MAT_BYTES)             // 81920

__global__ void __launch_bounds__(512, 1) gemm_mma(
    const float* __restrict__ A, const float* __restrict__ W,
    const float* __restrict__ bias, float* __restrict__ Y,
    int K, int N)
{
    extern __shared__ char sm[];
    __nv_bfloat16* Ah = (__nv_bfloat16*)(sm);
    __nv_bfloat16* Al = (__nv_bfloat16*)(sm + MAT_BYTES);
    __nv_bfloat16* Wh = (__nv_bfloat16*)(sm + 2 * MAT_BYTES);
    __nv_bfloat16* Wl = (__nv_bfloat16*)(sm + 3 * MAT_BYTES);

    const int tid = threadIdx.x;
    const int lane = tid & 31;
    const int wid = tid >> 5;
    const int wy = wid >> 2;
    const int wx = wid & 3;
    const int m0 = blockIdx.y * 128;
    const int n0 = blockIdx.x * 128;

    const int srow = tid >> 2;
    const int sk0 = (tid & 3) << 4;
    const float* aptr = A + (size_t)(m0 + srow) * K + sk0;
    const float* wptr = W + (size_t)(n0 + srow) * K + sk0;
    const int sidx = srow * GPITCH + sk0;

    float acc[2][4][4];
#pragma unroll
    for (int t = 0; t < 2; t++)
#pragma unroll
        for (int u = 0; u < 4; u++)
#pragma unroll
            for (int i = 0; i < 4; i++) acc[t][u][i] = 0.f;

    const int r8 = lane >> 2;
    const int q2 = (lane & 3) << 1;

    const int nchunk = K >> 6;
    for (int c = 0; c < nchunk; c++) {
        const int kc = c << 6;
        float4 va[4], vw[4];
#pragma unroll
        for (int i = 0; i < 4; i++) {
            va[i] = *(const float4*)(aptr + kc + i * 4);
            vw[i] = *(const float4*)(wptr + kc + i * 4);
        }
        __syncthreads();
#pragma unroll
        for (int i = 0; i < 4; i++) {
            cvt_store4(Ah, Al, sidx + i * 4, va[i]);
            cvt_store4(Wh, Wl, sidx + i * 4, vw[i]);
        }
        __syncthreads();

#pragma unroll
        for (int ks = 0; ks < 4; ks++) {
            const int kk = ks << 4;
            uint32_t ah[2][4], al[2][4];
#pragma unroll
            for (int t = 0; t < 2; t++) {
                const int base = (wy * 32 + t * 16 + r8) * GPITCH + q2 + kk;
                ah[t][0] = *(const uint32_t*)(Ah + base);
                ah[t][1] = *(const uint32_t*)(Ah + base + 8 * GPITCH);
                ah[t][2] = *(const uint32_t*)(Ah + base + 8);
                ah[t][3] = *(const uint32_t*)(Ah + base + 8 * GPITCH + 8);
                al[t][0] = *(const uint32_t*)(Al + base);
                al[t][1] = *(const uint32_t*)(Al + base + 8 * GPITCH);
                al[t][2] = *(const uint32_t*)(Al + base + 8);
                al[t][3] = *(const uint32_t*)(Al + base + 8 * GPITCH + 8);
            }
#pragma unroll
            for (int u = 0; u < 4; u++) {
                const int nb = (wx * 32 + u * 8 + r8) * GPITCH + q2 + kk;
                const uint32_t bh0 = *(const uint32_t*)(Wh + nb);
                const uint32_t bh1 = *(const uint32_t*)(Wh + nb + 8);
                const uint32_t bl0 = *(const uint32_t*)(Wl + nb);
                const uint32_t bl1 = *(const uint32_t*)(Wl + nb + 8);
#pragma unroll
                for (int t = 0; t < 2; t++) {
                    MMA_BF16(acc[t][u], ah[t][0], ah[t][1], ah[t][2], ah[t][3], bh0, bh1);
                    MMA_BF16(acc[t][u], ah[t][0], ah[t][1], ah[t][2], ah[t][3], bl0, bl1);
                    MMA_BF16(acc[t][u], al[t][0], al[t][1], al[t][2], al[t][3], bh0, bh1);
                }
            }
        }
    }

#pragma unroll
    for (int t = 0; t < 2; t++) {
        const int r0 = m0 + wy * 32 + t * 16 + r8;
#pragma unroll
        for (int u = 0; u < 4; u++) {
            const int col = n0 + wx * 32 + u * 8 + q2;
            const float b0 = bias[col], b1 = bias[col + 1];
            float2 v0, v1;
            v0.x = acc[t][u][0] + b0; v0.y = acc[t][u][1] + b1;
            v1.x = acc[t][u][2] + b0; v1.y = acc[t][u][3] + b1;
            *(float2*)(Y + (size_t)r0 * N + col) = v0;
            *(float2*)(Y + (size_t)(r0 + 8) * N + col) = v1;
        }
    }
}

// ============================================================================
// scores via mma: P[bh, q, k] = (Q . K) * 0.125, 128x128 tile, causal pairs
// smem: Qh|Ql|Kh|Kl each 128 x 64 bf16 pitch 72
// ============================================================================
#define SPITCH 72
#define SMAT_BYTES (128 * SPITCH * 2)         // 18432
#define SCORES_SMEM (4 * SMAT_BYTES)          // 73728

__global__ void __launch_bounds__(512, 1) scores_mma(void)
{
    // causal pair idx -> (qt, kt), kt <= qt, 16x16 tiles of 128
    int idx = blockIdx.x;
    int qt = 0;
    while ((qt + 1) * (qt + 2) / 2 <= idx) qt++;
    const int kt = idx - qt * (qt + 1) / 2;
    const int bh = blockIdx.y;
    const int b = bh >> 4;
    const int h = bh & 15;
    const int q0 = qt << 7;
    const int k0g = kt << 7;

    extern __shared__ char sm[];
    __nv_bfloat16* Qh = (__nv_bfloat16*)(sm);
    __nv_bfloat16* Ql = (__nv_bfloat16*)(sm + SMAT_BYTES);
    __nv_bfloat16* Kh = (__nv_bfloat16*)(sm + 2 * SMAT_BYTES);
    __nv_bfloat16* Kl = (__nv_bfloat16*)(sm + 3 * SMAT_BYTES);

    const int tid = threadIdx.x;
    const int lane = tid & 31;
    const int wid = tid >> 5;
    const int wy = wid >> 2;
    const int wx = wid & 3;

    // stage: thread -> (row = tid>>2, 16 k-values)
    {
        const int srow = tid >> 2;
        const int sk0 = (tid & 3) << 4;
        const float* qrow = g_Q + ((size_t)b * SS + q0 + srow) * DD + h * DK + sk0;
        const float* krow = g_K + ((size_t)b * SS + k0g + srow) * DD + h * DK + sk0;
        const int sidx = srow * SPITCH + sk0;
#pragma unroll
        for (int i = 0; i < 4; i++) {
            cvt_store4(Qh, Ql, sidx + i * 4, *(const float4*)(qrow + i * 4));
            cvt_store4(Kh, Kl, sidx + i * 4, *(const float4*)(krow + i * 4));
        }
    }
    __syncthreads();

    float acc[2][4][4];
#pragma unroll
    for (int t = 0; t < 2; t++)
#pragma unroll
        for (int u = 0; u < 4; u++)
#pragma unroll
            for (int i = 0; i < 4; i++) acc[t][u][i] = 0.f;

    const int r8 = lane >> 2;
    const int q2 = (lane & 3) << 1;

#pragma unroll
    for (int ks = 0; ks < 4; ks++) {
        const int kk = ks << 4;
        uint32_t ah[2][4], al[2][4];
#pragma unroll
        for (int t = 0; t < 2; t++) {
            const int base = (wy * 32 + t * 16 + r8) * SPITCH + q2 + kk;
            ah[t][0] = *(const uint32_t*)(Qh + base);
            ah[t][1] = *(const uint32_t*)(Qh + base + 8 * SPITCH);
            ah[t][2] = *(const uint32_t*)(Qh + base + 8);
            ah[t][3] = *(const uint32_t*)(Qh + base + 8 * SPITCH + 8);
            al[t][0] = *(const uint32_t*)(Ql + base);
            al[t][1] = *(const uint32_t*)(Ql + base + 8 * SPITCH);
            al[t][2] = *(const uint32_t*)(Ql + base + 8);
            al[t][3] = *(const uint32_t*)(Ql + base + 8 * SPITCH + 8);
        }
#pragma unroll
        for (int u = 0; u < 4; u++) {
            const int nb = (wx * 32 + u * 8 + r8) * SPITCH + q2 + kk;
            const uint32_t bh0 = *(const uint32_t*)(Kh + nb);
            const uint32_t bh1 = *(const uint32_t*)(Kh + nb + 8);
            const uint32_t bl0 = *(const uint32_t*)(Kl + nb);
            const uint32_t bl1 = *(const uint32_t*)(Kl + nb + 8);
#pragma unroll
            for (int t = 0; t < 2; t++) {
                MMA_BF16(acc[t][u], ah[t][0], ah[t][1], ah[t][2], ah[t][3], bh0, bh1);
                MMA_BF16(acc[t][u], ah[t][0], ah[t][1], ah[t][2], ah[t][3], bl0, bl1);
                MMA_BF16(acc[t][u], al[t][0], al[t][1], al[t][2], al[t][3], bh0, bh1);
            }
        }
    }

    const float scale = 0.125f;
#pragma unroll
    for (int t = 0; t < 2; t++) {
        const int r0 = q0 + wy * 32 + t * 16 + r8;
#pragma unroll
        for (int u = 0; u < 4; u++) {
            const int col = k0g + wx * 32 + u * 8 + q2;
            float2 v0, v1;
            v0.x = acc[t][u][0] * scale; v0.y = acc[t][u][1] * scale;
            v1.x = acc[t][u][2] * scale; v1.y = acc[t][u][3] * scale;
            *(float2*)(g_P + ((size_t)bh * SS + r0) * SS + col) = v0;
            *(float2*)(g_P + ((size_t)bh * SS + r0 + 8) * SS + col) = v1;
        }
    }
}

// ============================================================================
// softmax per row (causal), zero-fill only to the 128-tile boundary
// ============================================================================
__global__ __launch_bounds__(256) void softmax_kernel(void)
{
    const int row = blockIdx.x;
    const int q = row & (SS - 1);
    const int len = q + 1;
    const int bound = ((q >> 7) + 1) << 7;

    __shared__ float buf[SS];
    __shared__ float red[8];
    __shared__ float s_bcast;

    float* Prow = g_P + (size_t)row * SS;
    const int tid = threadIdx.x;
    const int lane = tid & 31, warp = tid >> 5;

    float m = -INFINITY;
    for (int k = tid; k < len; k += 256) {
        float v = Prow[k];
        buf[k] = v;
        m = fmaxf(m, v);
    }
#pragma unroll
    for (int o = 16; o; o >>= 1) m = fmaxf(m, __shfl_xor_sync(0xFFFFFFFFu, m, o));
    if (lane == 0) red[warp] = m;
    __syncthreads();
    if (tid == 0) {
        float t = red[0];
#pragma unroll
        for (int i = 1; i < 8; i++) t = fmaxf(t, red[i]);
        s_bcast = t;
    }
    __syncthreads();
    const float rowmax = s_bcast;
    __syncthreads();

    float s = 0.f;
    for (int k = tid; k < len; k += 256) {
        float e = __expf(buf[k] - rowmax);
        buf[k] = e;
        s += e;
    }
#pragma unroll
    for (int o = 16; o; o >>= 1) s += __shfl_xor_sync(0xFFFFFFFFu, s, o);
    if (lane == 0) red[warp] = s;
    __syncthreads();
    if (tid == 0) {
        float t = 0.f;
#pragma unroll
        for (int i = 0; i < 8; i++) t += red[i];
        s_bcast = t;
    }
    __syncthreads();
    const float inv = 1.0f / s_bcast;

    for (int k = tid; k < bound; k += 256)
        Prow[k] = (k < len) ? buf[k] * inv : 0.f;
}

// ============================================================================
// AW[b,q,k] = sum_h P[b,h,q,k]; zeros analytically for k > q
// ============================================================================
__global__ __launch_bounds__(256) void aw_kernel(float* __restrict__ AW)
{
    const size_t idx = (size_t)blockIdx.x * 256 + threadIdx.x;
    const size_t k4 = (idx % (SS / 4)) * 4;
    const size_t q = (idx / (SS / 4)) % SS;
    const size_t b = idx / ((size_t)(SS / 4) * SS);

    float4 s = make_float4(0.f, 0.f, 0.f, 0.f);
    if (k4 <= q) {
#pragma unroll
        for (int h = 0; h < HH; h++) {
            const float4 v = *(const float4*)(g_P + (((size_t)(b * HH + h) * SS + q) * SS + k4));
            s.x += v.x; s.y += v.y; s.z += v.z; s.w += v.w;
        }
    }
    *(float4*)(AW + ((size_t)b * SS + q) * SS + k4) = s;
}

// ============================================================================
// pv via mma: C[b, q, h*64+d] = sum_k P[bh,q,k] * V[b,k,h*64+d]  (V = g_K)
// CTA: (qt128, bh), C tile 128x64, K-chunks of 64, 512 thr / 16 warps
// warp tile 16x32 (wy=wid>>1 rows, wx=wid&1 cols)
// smem: Ph|Pl 128x64 pitch 72; Vth|Vtl 64x64 pitch 72 (V transposed: [d][k])
// ============================================================================
#define PV_PBYTES (128 * SPITCH * 2)          // 18432
#define PV_VBYTES (64 * SPITCH * 2)           // 9216
#define PV_SMEM (2 * PV_PBYTES + 2 * PV_VBYTES)  // 55296

__global__ void __launch_bounds__(512, 1) pv_mma(void)
{
    const int qt = blockIdx.x;                // 0..15 (128-row tiles)
    const int bh = blockIdx.y;
    const int b = bh >> 4;
    const int h = bh & 15;
    const int q0 = qt << 7;

    extern __shared__ char sm[];
    __nv_bfloat16* Ph  = (__nv_bfloat16*)(sm);
    __nv_bfloat16* Pl  = (__nv_bfloat16*)(sm + PV_PBYTES);
    __nv_bfloat16* Vth = (__nv_bfloat16*)(sm + 2 * PV_PBYTES);
    __nv_bfloat16* Vtl = (__nv_bfloat16*)(sm + 2 * PV_PBYTES + PV_VBYTES);

    const int tid = threadIdx.x;
    const int lane = tid & 31;
    const int wid = tid >> 5;
    const int wy = wid >> 1;                  // 0..7 -> 16 rows each
    const int wx = wid & 1;                   // 0..1 -> 32 cols each

    const int r8 = lane >> 2;
    const int q2 = (lane & 3) << 1;

    float acc[4][4];
#pragma unroll
    for (int u = 0; u < 4; u++)
#pragma unroll
        for (int i = 0; i < 4; i++) acc[u][i] = 0.f;

    // staging maps
    const int prow_s = tid >> 2;              // 0..127
    const int pk0 = (tid & 3) << 4;           // 0,16,32,48
    const int vrow_s = tid >> 3;              // 0..63 (k within chunk)
    const int vd0 = (tid & 7) << 3;           // 0,8,..,56

    const int nchunk = 2 * qt + 2;            // covers k < (qt+1)*128 (zero-padded by softmax)
    for (int kt = 0; kt < nchunk; kt++) {
        const int kc = kt << 6;
        // loads (issued before sync to overlap with previous compute)
        float4 pv4[4];
#pragma unroll
        for (int i = 0; i < 4; i++)
            pv4[i] = *(const float4*)(g_P + ((size_t)bh * SS + q0 + prow_s) * SS + kc + pk0 + i * 4);
        float vv[8];
        {
            const float* vr = g_K + ((size_t)b * SS + kc + vrow_s) * DD + h * DK + vd0;
            float4 a = *(const float4*)(vr);
            float4 c = *(const float4*)(vr + 4);
            vv[0] = a.x; vv[1] = a.y; vv[2] = a.z; vv[3] = a.w;
            vv[4] = c.x; vv[5] = c.y; vv[6] = c.z; vv[7] = c.w;
        }
        __syncthreads();
#pragma unroll
        for (int i = 0; i < 4; i++)
            cvt_store4(Ph, Pl, prow_s * SPITCH + pk0 + i * 4, pv4[i]);
#pragma unroll
        for (int i = 0; i < 8; i++) {
            const int d = vd0 + i;
            __nv_bfloat16 hi = __float2bfloat16_rn(vv[i]);
            __nv_bfloat16 lo = __float2bfloat16_rn(vv[i] - __bfloat162float(hi));
            Vth[d * SPITCH + vrow_s] = hi;
            Vtl[d * SPITCH + vrow_s] = lo;
        }
        __syncthreads();

#pragma unroll
        for (int ks = 0; ks < 4; ks++) {
            const int kk = ks << 4;
            uint32_t ah[4], al[4];
            {
                const int base = (wy * 16 + r8) * SPITCH + q2 + kk;
                ah[0] = *(const uint32_t*)(Ph + base);
                ah[1] = *(const uint32_t*)(Ph + base + 8 * SPITCH);
                ah[2] = *(const uint32_t*)(Ph + base + 8);
                ah[3] = *(const uint32_t*)(Ph + base + 8 * SPITCH + 8);
                al[0] = *(const uint32_t*)(Pl + base);
                al[1] = *(const uint32_t*)(Pl + base + 8 * SPITCH);
                al[2] = *(const uint32_t*)(Pl + base + 8);
                al[3] = *(const uint32_t*)(Pl + base + 8 * SPITCH + 8);
            }
#pragma unroll
            for (int u = 0; u < 4; u++) {
                const int nb = (wx * 32 + u * 8 + r8) * SPITCH + q2 + kk;
                const uint32_t bh0 = *(const uint32_t*)(Vth + nb);
                const uint32_t bh1 = *(const uint32_t*)(Vth + nb + 8);
                const uint32_t bl0 = *(const uint32_t*)(Vtl + nb);
                const uint32_t bl1 = *(const uint32_t*)(Vtl + nb + 8);
                MMA_BF16(acc[u], ah[0], ah[1], ah[2], ah[3], bh0, bh1);
                MMA_BF16(acc[u], ah[0], ah[1], ah[2], ah[3], bl0, bl1);
                MMA_BF16(acc[u], al[0], al[1], al[2], al[3], bh0, bh1);
            }
        }
    }

    // epilogue -> g_C
    const int r0 = q0 + wy * 16 + r8;
#pragma unroll
    for (int u = 0; u < 4; u++) {
        const int d = wx * 32 + u * 8 + q2;
        float* c0 = g_C + ((size_t)b * SS + r0) * DD + h * DK + d;
        float* c1 = g_C + ((size_t)b * SS + r0 + 8) * DD + h * DK + d;
        c0[0] = acc[u][0]; c0[1] = acc[u][1];
        c1[0] = acc[u][2]; c1[1] = acc[u][3];
    }
}

// ============================================================================
// launch
// ============================================================================
extern "C" void kernel_launch(void* const* d_in, const int* in_sizes, int n_in,
                              void* d_out, int out_size)
{
    const float* x    = (const float*)d_in[0];
    const float* z    = (const float*)d_in[1];
    // d_in[2] = mask (causal tril; handled analytically)
    const float* wq_w = (const float*)d_in[3];
    const float* wq_b = (const float*)d_in[4];
    const float* wk_w = (const float*)d_in[5];
    const float* wk_b = (const float*)d_in[6];
    // d_in[7], d_in[8] = wv (dead param in reference: v uses wk)
    const float* wo_w = (const float*)d_in[9];
    const float* wo_b = (const float*)d_in[10];

    float* out = (float*)d_out;                              // [B,S,D]
    float* AW  = out + (size_t)BB * SS * DD;                 // [B,S,S]

    float *pQ, *pK, *pC;
    cudaGetSymbolAddress((void**)&pQ, g_Q);
    cudaGetSymbolAddress((void**)&pK, g_K);
    cudaGetSymbolAddress((void**)&pC, g_C);

    static int smem_set = 0;
    if (!smem_set) {
        cudaFuncSetAttribute(gemm_mma, cudaFuncAttributeMaxDynamicSharedMemorySize, GEMM_SMEM);
        cudaFuncSetAttribute(scores_mma, cudaFuncAttributeMaxDynamicSharedMemorySize, SCORES_SMEM);
        cudaFuncSetAttribute(pv_mma, cudaFuncAttributeMaxDynamicSharedMemorySize, PV_SMEM);
        smem_set = 1;
    }

    const dim3 gProj(DD / 128, MROWS / 128);                 // (8,32)
    gemm_mma<<<gProj, 512, GEMM_SMEM>>>(x, wq_w, wq_b, pQ, DD, DD);
    gemm_mma<<<gProj, 512, GEMM_SMEM>>>(z, wk_w, wk_b, pK, DD, DD);

    scores_mma<<<dim3(136, BHT), 512, SCORES_SMEM>>>();      // causal 128-tiles

    softmax_kernel<<<BHT * SS, 256>>>();

    aw_kernel<<<(BB * SS * (SS / 4)) / 256, 256>>>(AW);

    pv_mma<<<dim3(16, BHT), 512, PV_SMEM>>>();

    gemm_mma<<<gProj, 512, GEMM_SMEM>>>(pC, wo_w, wo_b, out, DD, DD);
}

// round 6
// speedup vs baseline: 1.9206x; 1.1191x over previous
#include <cuda_runtime.h>
#include <cuda_bf16.h>
#include <cstdint>
#include <math.h>

// Problem dims
#define BB 2
#define SS 2048
#define DD 1024
#define HH 16
#define DK 64
#define MROWS (BB * SS)   // 4096
#define BHT (BB * HH)     // 32

// -------- scratch (static __device__ globals; no allocation allowed) --------
__device__ float g_P[(size_t)BB * HH * SS * SS];            // 512 MB attn probs (fp32)

// bf16 hi/lo planes
__device__ __nv_bfloat16 g_Xh[(size_t)MROWS * DD], g_Xl[(size_t)MROWS * DD];
__device__ __nv_bfloat16 g_Zh[(size_t)MROWS * DD], g_Zl[(size_t)MROWS * DD];
__device__ __nv_bfloat16 g_Qh[(size_t)MROWS * DD], g_Ql[(size_t)MROWS * DD];
__device__ __nv_bfloat16 g_Kh[(size_t)MROWS * DD], g_Kl[(size_t)MROWS * DD];
__device__ __nv_bfloat16 g_Ch[(size_t)MROWS * DD], g_Cl[(size_t)MROWS * DD];
__device__ __nv_bfloat16 g_Wqh[(size_t)DD * DD], g_Wql[(size_t)DD * DD];
__device__ __nv_bfloat16 g_Wkh[(size_t)DD * DD], g_Wkl[(size_t)DD * DD];
__device__ __nv_bfloat16 g_Woh[(size_t)DD * DD], g_Wol[(size_t)DD * DD];

// ============================================================================
// helpers
// ============================================================================
__device__ __forceinline__ uint32_t pack_bf16(__nv_bfloat16 a, __nv_bfloat16 b) {
    return (uint32_t)__bfloat16_as_ushort(a) | ((uint32_t)__bfloat16_as_ushort(b) << 16);
}

__device__ __forceinline__ void split1(float v, __nv_bfloat16& h, __nv_bfloat16& l) {
    h = __float2bfloat16_rn(v);
    l = __float2bfloat16_rn(v - __bfloat162float(h));
}

__device__ __forceinline__ void cvt_store4(__nv_bfloat16* H, __nv_bfloat16* L,
                                           int idx, float4 v) {
    __nv_bfloat16 h0, h1, h2, h3, l0, l1, l2, l3;
    split1(v.x, h0, l0); split1(v.y, h1, l1);
    split1(v.z, h2, l2); split1(v.w, h3, l3);
    *(uint32_t*)(H + idx)     = pack_bf16(h0, h1);
    *(uint32_t*)(H + idx + 2) = pack_bf16(h2, h3);
    *(uint32_t*)(L + idx)     = pack_bf16(l0, l1);
    *(uint32_t*)(L + idx + 2) = pack_bf16(l2, l3);
}

#define MMA_BF16(C, A0, A1, A2, A3, B0, B1) \
    asm volatile( \
        "mma.sync.aligned.m16n8k16.row.col.f32.bf16.bf16.f32 " \
        "{%0,%1,%2,%3}, {%4,%5,%6,%7}, {%8,%9}, {%0,%1,%2,%3};" \
        : "+f"((C)[0]), "+f"((C)[1]), "+f"((C)[2]), "+f"((C)[3]) \
        : "r"(A0), "r"(A1), "r"(A2), "r"(A3), "r"(B0), "r"(B1))

// ============================================================================
// fp32 -> bf16 hi/lo split (4 elements / thread)
// ============================================================================
__global__ __launch_bounds__(256) void cvt_split(
    const float* __restrict__ src,
    __nv_bfloat16* __restrict__ hi, __nv_bfloat16* __restrict__ lo)
{
    const size_t i4 = ((size_t)blockIdx.x * 256 + threadIdx.x) * 4;
    const float4 v = *(const float4*)(src + i4);
    __nv_bfloat16 h0, h1, h2, h3, l0, l1, l2, l3;
    split1(v.x, h0, l0); split1(v.y, h1, l1);
    split1(v.z, h2, l2); split1(v.w, h3, l3);
    uint2 ph, pl;
    ph.x = pack_bf16(h0, h1); ph.y = pack_bf16(h2, h3);
    pl.x = pack_bf16(l0, l1); pl.y = pack_bf16(l2, l3);
    *(uint2*)(hi + i4) = ph;
    *(uint2*)(lo + i4) = pl;
}

// ============================================================================
// bf16x3 GEMM from pre-split planes: Y = A @ W^T + bias
// 512 thr / 16 warps, CTA 128x128, warp 32x32, K-chunk 64
// OUTF32: write fp32 Y; else write bf16 hi/lo planes Yh/Yl
// ============================================================================
#define GPITCH 80
#define MAT_BYTES (128 * GPITCH * 2)          // 20480
#define GEMM_SMEM (4 * MAT_BYTES)             // 81920

template<bool OUTF32>
__global__ void __launch_bounds__(512, 1) gemm_pre(
    const __nv_bfloat16* __restrict__ Ah_g, const __nv_bfloat16* __restrict__ Al_g,
    const __nv_bfloat16* __restrict__ Wh_g, const __nv_bfloat16* __restrict__ Wl_g,
    const float* __restrict__ bias,
    float* __restrict__ Y,
    __nv_bfloat16* __restrict__ Yh, __nv_bfloat16* __restrict__ Yl,
    int K, int N)
{
    extern __shared__ char sm[];
    __nv_bfloat16* Ah = (__nv_bfloat16*)(sm);
    __nv_bfloat16* Al = (__nv_bfloat16*)(sm + MAT_BYTES);
    __nv_bfloat16* Wh = (__nv_bfloat16*)(sm + 2 * MAT_BYTES);
    __nv_bfloat16* Wl = (__nv_bfloat16*)(sm + 3 * MAT_BYTES);

    const int tid = threadIdx.x;
    const int lane = tid & 31;
    const int wid = tid >> 5;
    const int wy = wid >> 2;
    const int wx = wid & 3;
    const int m0 = blockIdx.y * 128;
    const int n0 = blockIdx.x * 128;

    const int srow = tid >> 2;
    const int sk0 = (tid & 3) << 4;
    const __nv_bfloat16* pAh = Ah_g + (size_t)(m0 + srow) * K + sk0;
    const __nv_bfloat16* pAl = Al_g + (size_t)(m0 + srow) * K + sk0;
    const __nv_bfloat16* pWh = Wh_g + (size_t)(n0 + srow) * K + sk0;
    const __nv_bfloat16* pWl = Wl_g + (size_t)(n0 + srow) * K + sk0;
    const int sidx = srow * GPITCH + sk0;

    float acc[2][4][4];
#pragma unroll
    for (int t = 0; t < 2; t++)
#pragma unroll
        for (int u = 0; u < 4; u++)
#pragma unroll
            for (int i = 0; i < 4; i++) acc[t][u][i] = 0.f;

    const int r8 = lane >> 2;
    const int q2 = (lane & 3) << 1;

    const int nchunk = K >> 6;
    for (int c = 0; c < nchunk; c++) {
        const int kc = c << 6;
        const uint4 ah0 = *(const uint4*)(pAh + kc);
        const uint4 ah1 = *(const uint4*)(pAh + kc + 8);
        const uint4 al0 = *(const uint4*)(pAl + kc);
        const uint4 al1 = *(const uint4*)(pAl + kc + 8);
        const uint4 wh0 = *(const uint4*)(pWh + kc);
        const uint4 wh1 = *(const uint4*)(pWh + kc + 8);
        const uint4 wl0 = *(const uint4*)(pWl + kc);
        const uint4 wl1 = *(const uint4*)(pWl + kc + 8);
        __syncthreads();                    // prev compute done reading smem
        *(uint4*)(Ah + sidx)     = ah0; *(uint4*)(Ah + sidx + 8) = ah1;
        *(uint4*)(Al + sidx)     = al0; *(uint4*)(Al + sidx + 8) = al1;
        *(uint4*)(Wh + sidx)     = wh0; *(uint4*)(Wh + sidx + 8) = wh1;
        *(uint4*)(Wl + sidx)     = wl0; *(uint4*)(Wl + sidx + 8) = wl1;
        __syncthreads();

#pragma unroll
        for (int ks = 0; ks < 4; ks++) {
            const int kk = ks << 4;
            uint32_t ahf[2][4], alf[2][4];
#pragma unroll
            for (int t = 0; t < 2; t++) {
                const int base = (wy * 32 + t * 16 + r8) * GPITCH + q2 + kk;
                ahf[t][0] = *(const uint32_t*)(Ah + base);
                ahf[t][1] = *(const uint32_t*)(Ah + base + 8 * GPITCH);
                ahf[t][2] = *(const uint32_t*)(Ah + base + 8);
                ahf[t][3] = *(const uint32_t*)(Ah + base + 8 * GPITCH + 8);
                alf[t][0] = *(const uint32_t*)(Al + base);
                alf[t][1] = *(const uint32_t*)(Al + base + 8 * GPITCH);
                alf[t][2] = *(const uint32_t*)(Al + base + 8);
                alf[t][3] = *(const uint32_t*)(Al + base + 8 * GPITCH + 8);
            }
#pragma unroll
            for (int u = 0; u < 4; u++) {
                const int nb = (wx * 32 + u * 8 + r8) * GPITCH + q2 + kk;
                const uint32_t bh0 = *(const uint32_t*)(Wh + nb);
                const uint32_t bh1 = *(const uint32_t*)(Wh + nb + 8);
                const uint32_t bl0 = *(const uint32_t*)(Wl + nb);
                const uint32_t bl1 = *(const uint32_t*)(Wl + nb + 8);
#pragma unroll
                for (int t = 0; t < 2; t++) {
                    MMA_BF16(acc[t][u], ahf[t][0], ahf[t][1], ahf[t][2], ahf[t][3], bh0, bh1);
                    MMA_BF16(acc[t][u], ahf[t][0], ahf[t][1], ahf[t][2], ahf[t][3], bl0, bl1);
                    MMA_BF16(acc[t][u], alf[t][0], alf[t][1], alf[t][2], alf[t][3], bh0, bh1);
                }
            }
        }
    }

#pragma unroll
    for (int t = 0; t < 2; t++) {
        const int r0 = m0 + wy * 32 + t * 16 + r8;
#pragma unroll
        for (int u = 0; u < 4; u++) {
            const int col = n0 + wx * 32 + u * 8 + q2;
            const float b0 = bias[col], b1 = bias[col + 1];
            const float v00 = acc[t][u][0] + b0, v01 = acc[t][u][1] + b1;
            const float v10 = acc[t][u][2] + b0, v11 = acc[t][u][3] + b1;
            if (OUTF32) {
                *(float2*)(Y + (size_t)r0 * N + col) = make_float2(v00, v01);
                *(float2*)(Y + (size_t)(r0 + 8) * N + col) = make_float2(v10, v11);
            } else {
                __nv_bfloat16 h0, h1, l0, l1;
                split1(v00, h0, l0); split1(v01, h1, l1);
                *(uint32_t*)(Yh + (size_t)r0 * N + col) = pack_bf16(h0, h1);
                *(uint32_t*)(Yl + (size_t)r0 * N + col) = pack_bf16(l0, l1);
                split1(v10, h0, l0); split1(v11, h1, l1);
                *(uint32_t*)(Yh + (size_t)(r0 + 8) * N + col) = pack_bf16(h0, h1);
                *(uint32_t*)(Yl + (size_t)(r0 + 8) * N + col) = pack_bf16(l0, l1);
            }
        }
    }
}

// ============================================================================
// scores: P = (Q.K^T)*0.125 from pre-split planes, 128x128 causal tiles
// ============================================================================
#define SPITCH 72
#define SMAT_BYTES (128 * SPITCH * 2)         // 18432
#define SCORES_SMEM (4 * SMAT_BYTES)          // 73728

__global__ void __launch_bounds__(512, 1) scores_mma(void)
{
    int idx = blockIdx.x;
    int qt = 0;
    while ((qt + 1) * (qt + 2) / 2 <= idx) qt++;
    const int kt = idx - qt * (qt + 1) / 2;
    const int bh = blockIdx.y;
    const int b = bh >> 4;
    const int h = bh & 15;
    const int q0 = qt << 7;
    const int k0g = kt << 7;

    extern __shared__ char sm[];
    __nv_bfloat16* Qh = (__nv_bfloat16*)(sm);
    __nv_bfloat16* Ql = (__nv_bfloat16*)(sm + SMAT_BYTES);
    __nv_bfloat16* Kh = (__nv_bfloat16*)(sm + 2 * SMAT_BYTES);
    __nv_bfloat16* Kl = (__nv_bfloat16*)(sm + 3 * SMAT_BYTES);

    const int tid = threadIdx.x;
    const int lane = tid & 31;
    const int wid = tid >> 5;
    const int wy = wid >> 2;
    const int wx = wid & 3;

    {
        const int srow = tid >> 2;
        const int sk0 = (tid & 3) << 4;
        const size_t qoff = ((size_t)b * SS + q0 + srow) * DD + h * DK + sk0;
        const size_t koff = ((size_t)b * SS + k0g + srow) * DD + h * DK + sk0;
        const int sidx = srow * SPITCH + sk0;
        *(uint4*)(Qh + sidx)     = *(const uint4*)(g_Qh + qoff);
        *(uint4*)(Qh + sidx + 8) = *(const uint4*)(g_Qh + qoff + 8);
        *(uint4*)(Ql + sidx)     = *(const uint4*)(g_Ql + qoff);
        *(uint4*)(Ql + sidx + 8) = *(const uint4*)(g_Ql + qoff + 8);
        *(uint4*)(Kh + sidx)     = *(const uint4*)(g_Kh + koff);
        *(uint4*)(Kh + sidx + 8) = *(const uint4*)(g_Kh + koff + 8);
        *(uint4*)(Kl + sidx)     = *(const uint4*)(g_Kl + koff);
        *(uint4*)(Kl + sidx + 8) = *(const uint4*)(g_Kl + koff + 8);
    }
    __syncthreads();

    float acc[2][4][4];
#pragma unroll
    for (int t = 0; t < 2; t++)
#pragma unroll
        for (int u = 0; u < 4; u++)
#pragma unroll
            for (int i = 0; i < 4; i++) acc[t][u][i] = 0.f;

    const int r8 = lane >> 2;
    const int q2 = (lane & 3) << 1;

#pragma unroll
    for (int ks = 0; ks < 4; ks++) {
        const int kk = ks << 4;
        uint32_t ah[2][4], al[2][4];
#pragma unroll
        for (int t = 0; t < 2; t++) {
            const int base = (wy * 32 + t * 16 + r8) * SPITCH + q2 + kk;
            ah[t][0] = *(const uint32_t*)(Qh + base);
            ah[t][1] = *(const uint32_t*)(Qh + base + 8 * SPITCH);
            ah[t][2] = *(const uint32_t*)(Qh + base + 8);
            ah[t][3] = *(const uint32_t*)(Qh + base + 8 * SPITCH + 8);
            al[t][0] = *(const uint32_t*)(Ql + base);
            al[t][1] = *(const uint32_t*)(Ql + base + 8 * SPITCH);
            al[t][2] = *(const uint32_t*)(Ql + base + 8);
            al[t][3] = *(const uint32_t*)(Ql + base + 8 * SPITCH + 8);
        }
#pragma unroll
        for (int u = 0; u < 4; u++) {
            const int nb = (wx * 32 + u * 8 + r8) * SPITCH + q2 + kk;
            const uint32_t bh0 = *(const uint32_t*)(Kh + nb);
            const uint32_t bh1 = *(const uint32_t*)(Kh + nb + 8);
            const uint32_t bl0 = *(const uint32_t*)(Kl + nb);
            const uint32_t bl1 = *(const uint32_t*)(Kl + nb + 8);
#pragma unroll
            for (int t = 0; t < 2; t++) {
                MMA_BF16(acc[t][u], ah[t][0], ah[t][1], ah[t][2], ah[t][3], bh0, bh1);
                MMA_BF16(acc[t][u], ah[t][0], ah[t][1], ah[t][2], ah[t][3], bl0, bl1);
                MMA_BF16(acc[t][u], al[t][0], al[t][1], al[t][2], al[t][3], bh0, bh1);
            }
        }
    }

    const float scale = 0.125f;
#pragma unroll
    for (int t = 0; t < 2; t++) {
        const int r0 = q0 + wy * 32 + t * 16 + r8;
#pragma unroll
        for (int u = 0; u < 4; u++) {
            const int col = k0g + wx * 32 + u * 8 + q2;
            float2 v0, v1;
            v0.x = acc[t][u][0] * scale; v0.y = acc[t][u][1] * scale;
            v1.x = acc[t][u][2] * scale; v1.y = acc[t][u][3] * scale;
            *(float2*)(g_P + ((size_t)bh * SS + r0) * SS + col) = v0;
            *(float2*)(g_P + ((size_t)bh * SS + r0 + 8) * SS + col) = v1;
        }
    }
}

// ============================================================================
// fused softmax + AW: one block per (b,q), loops over 16 heads.
// Normalizes P rows in-place (zero-filled to 128-boundary) and writes
// AW[b,q,:] = sum_h P[b,h,q,:].
// ============================================================================
__global__ __launch_bounds__(256) void softmax_aw(float* __restrict__ AW)
{
    const int q = blockIdx.x & (SS - 1);
    const int b = blockIdx.x >> 11;
    const int len = q + 1;
    const int bound = ((q >> 7) + 1) << 7;

    __shared__ float buf[SS];
    __shared__ float awr[SS];
    __shared__ float red[8];
    __shared__ float s_bcast;

    const int tid = threadIdx.x;
    const int lane = tid & 31, warp = tid >> 5;

    for (int k = tid; k < bound; k += 256) awr[k] = 0.f;
    __syncthreads();

    for (int h = 0; h < HH; h++) {
        float* Prow = g_P + (((size_t)(b * HH + h) * SS + q)) * SS;

        float m = -INFINITY;
        for (int k = tid; k < len; k += 256) {
            float v = Prow[k];
            buf[k] = v;
            m = fmaxf(m, v);
        }
#pragma unroll
        for (int o = 16; o; o >>= 1) m = fmaxf(m, __shfl_xor_sync(0xFFFFFFFFu, m, o));
        if (lane == 0) red[warp] = m;
        __syncthreads();
        if (tid == 0) {
            float t = red[0];
#pragma unroll
            for (int i = 1; i < 8; i++) t = fmaxf(t, red[i]);
            s_bcast = t;
        }
        __syncthreads();
        const float rowmax = s_bcast;
        __syncthreads();

        float s = 0.f;
        for (int k = tid; k < len; k += 256) {
            float e = __expf(buf[k] - rowmax);
            buf[k] = e;
            s += e;
        }
#pragma unroll
        for (int o = 16; o; o >>= 1) s += __shfl_xor_sync(0xFFFFFFFFu, s, o);
        if (lane == 0) red[warp] = s;
        __syncthreads();
        if (tid == 0) {
            float t = 0.f;
#pragma unroll
            for (int i = 0; i < 8; i++) t += red[i];
            s_bcast = t;
        }
        __syncthreads();
        const float inv = 1.0f / s_bcast;

        for (int k = tid; k < bound; k += 256) {
            const float v = (k < len) ? buf[k] * inv : 0.f;
            Prow[k] = v;
            awr[k] += v;
        }
        __syncthreads();   // red/s_bcast reuse next head
    }

    float* AWrow = AW + ((size_t)b * SS + q) * SS;
    for (int k = tid; k < SS; k += 256)
        AWrow[k] = (k < bound) ? awr[k] : 0.f;
}

// ============================================================================
// pv: C = P @ V (V = K planes); C written as bf16 hi/lo planes
// CTA: (qt128, bh), 512 thr, warp tile 16x32
// ============================================================================
#define PV_PBYTES (128 * SPITCH * 2)
#define PV_VBYTES (64 * SPITCH * 2)
#define PV_SMEM (2 * PV_PBYTES + 2 * PV_VBYTES)  // 55296

__global__ void __launch_bounds__(512, 1) pv_mma(void)
{
    const int qt = blockIdx.x;
    const int bh = blockIdx.y;
    const int b = bh >> 4;
    const int h = bh & 15;
    const int q0 = qt << 7;

    extern __shared__ char sm[];
    __nv_bfloat16* Ph  = (__nv_bfloat16*)(sm);
    __nv_bfloat16* Pl  = (__nv_bfloat16*)(sm + PV_PBYTES);
    __nv_bfloat16* Vth = (__nv_bfloat16*)(sm + 2 * PV_PBYTES);
    __nv_bfloat16* Vtl = (__nv_bfloat16*)(sm + 2 * PV_PBYTES + PV_VBYTES);

    const int tid = threadIdx.x;
    const int lane = tid & 31;
    const int wid = tid >> 5;
    const int wy = wid >> 1;
    const int wx = wid & 1;

    const int r8 = lane >> 2;
    const int q2 = (lane & 3) << 1;

    float acc[4][4];
#pragma unroll
    for (int u = 0; u < 4; u++)
#pragma unroll
        for (int i = 0; i < 4; i++) acc[u][i] = 0.f;

    const int prow_s = tid >> 2;
    const int pk0 = (tid & 3) << 4;
    const int vrow_s = tid >> 3;
    const int vd0 = (tid & 7) << 3;

    const int nchunk = 2 * qt + 2;
    for (int kt = 0; kt < nchunk; kt++) {
        const int kc = kt << 6;
        float4 pv4[4];
#pragma unroll
        for (int i = 0; i < 4; i++)
            pv4[i] = *(const float4*)(g_P + ((size_t)bh * SS + q0 + prow_s) * SS + kc + pk0 + i * 4);
        const size_t voff = ((size_t)b * SS + kc + vrow_s) * DD + h * DK + vd0;
        const uint4 vh = *(const uint4*)(g_Kh + voff);
        const uint4 vl = *(const uint4*)(g_Kl + voff);
        __syncthreads();
#pragma unroll
        for (int i = 0; i < 4; i++)
            cvt_store4(Ph, Pl, prow_s * SPITCH + pk0 + i * 4, pv4[i]);
        {
            const __nv_bfloat16* hv = (const __nv_bfloat16*)&vh;
            const __nv_bfloat16* lv = (const __nv_bfloat16*)&vl;
#pragma unroll
            for (int i = 0; i < 8; i++) {
                Vth[(vd0 + i) * SPITCH + vrow_s] = hv[i];
                Vtl[(vd0 + i) * SPITCH + vrow_s] = lv[i];
            }
        }
        __syncthreads();

#pragma unroll
        for (int ks = 0; ks < 4; ks++) {
            const int kk = ks << 4;
            uint32_t ah[4], al[4];
            {
                const int base = (wy * 16 + r8) * SPITCH + q2 + kk;
                ah[0] = *(const uint32_t*)(Ph + base);
                ah[1] = *(const uint32_t*)(Ph + base + 8 * SPITCH);
                ah[2] = *(const uint32_t*)(Ph + base + 8);
                ah[3] = *(const uint32_t*)(Ph + base + 8 * SPITCH + 8);
                al[0] = *(const uint32_t*)(Pl + base);
                al[1] = *(const uint32_t*)(Pl + base + 8 * SPITCH);
                al[2] = *(const uint32_t*)(Pl + base + 8);
                al[3] = *(const uint32_t*)(Pl + base + 8 * SPITCH + 8);
            }
#pragma unroll
            for (int u = 0; u < 4; u++) {
                const int nb = (wx * 32 + u * 8 + r8) * SPITCH + q2 + kk;
                const uint32_t bh0 = *(const uint32_t*)(Vth + nb);
                const uint32_t bh1 = *(const uint32_t*)(Vth + nb + 8);
                const uint32_t bl0 = *(const uint32_t*)(Vtl + nb);
                const uint32_t bl1 = *(const uint32_t*)(Vtl + nb + 8);
                MMA_BF16(acc[u], ah[0], ah[1], ah[2], ah[3], bh0, bh1);
                MMA_BF16(acc[u], ah[0], ah[1], ah[2], ah[3], bl0, bl1);
                MMA_BF16(acc[u], al[0], al[1], al[2], al[3], bh0, bh1);
            }
        }
    }

    // epilogue -> C bf16 hi/lo planes
    const int r0 = q0 + wy * 16 + r8;
#pragma unroll
    for (int u = 0; u < 4; u++) {
        const int d = wx * 32 + u * 8 + q2;
        const size_t o0 = ((size_t)b * SS + r0) * DD + h * DK + d;
        const size_t o1 = ((size_t)b * SS + r0 + 8) * DD + h * DK + d;
        __nv_bfloat16 h0, h1, l0, l1;
        split1(acc[u][0], h0, l0); split1(acc[u][1], h1, l1);
        *(uint32_t*)(g_Ch + o0) = pack_bf16(h0, h1);
        *(uint32_t*)(g_Cl + o0) = pack_bf16(l0, l1);
        split1(acc[u][2], h0, l0); split1(acc[u][3], h1, l1);
        *(uint32_t*)(g_Ch + o1) = pack_bf16(h0, h1);
        *(uint32_t*)(g_Cl + o1) = pack_bf16(l0, l1);
    }
}

// ============================================================================
// launch
// ============================================================================
extern "C" void kernel_launch(void* const* d_in, const int* in_sizes, int n_in,
                              void* d_out, int out_size)
{
    const float* x    = (const float*)d_in[0];
    const float* z    = (const float*)d_in[1];
    // d_in[2] = mask (causal tril; handled analytically)
    const float* wq_w = (const float*)d_in[3];
    const float* wq_b = (const float*)d_in[4];
    const float* wk_w = (const float*)d_in[5];
    const float* wk_b = (const float*)d_in[6];
    // d_in[7], d_in[8] = wv (dead param in reference: v uses wk)
    const float* wo_w = (const float*)d_in[9];
    const float* wo_b = (const float*)d_in[10];

    float* out = (float*)d_out;                              // [B,S,D]
    float* AW  = out + (size_t)BB * SS * DD;                 // [B,S,S]

    __nv_bfloat16 *pXh, *pXl, *pZh, *pZl, *pQh, *pQl, *pKh, *pKl, *pCh, *pCl;
    __nv_bfloat16 *pWqh, *pWql, *pWkh, *pWkl, *pWoh, *pWol;
    cudaGetSymbolAddress((void**)&pXh, g_Xh); cudaGetSymbolAddress((void**)&pXl, g_Xl);
    cudaGetSymbolAddress((void**)&pZh, g_Zh); cudaGetSymbolAddress((void**)&pZl, g_Zl);
    cudaGetSymbolAddress((void**)&pQh, g_Qh); cudaGetSymbolAddress((void**)&pQl, g_Ql);
    cudaGetSymbolAddress((void**)&pKh, g_Kh); cudaGetSymbolAddress((void**)&pKl, g_Kl);
    cudaGetSymbolAddress((void**)&pCh, g_Ch); cudaGetSymbolAddress((void**)&pCl, g_Cl);
    cudaGetSymbolAddress((void**)&pWqh, g_Wqh); cudaGetSymbolAddress((void**)&pWql, g_Wql);
    cudaGetSymbolAddress((void**)&pWkh, g_Wkh); cudaGetSymbolAddress((void**)&pWkl, g_Wkl);
    cudaGetSymbolAddress((void**)&pWoh, g_Woh); cudaGetSymbolAddress((void**)&pWol, g_Wol);

    static int smem_set = 0;
    if (!smem_set) {
        cudaFuncSetAttribute(gemm_pre<true>,  cudaFuncAttributeMaxDynamicSharedMemorySize, GEMM_SMEM);
        cudaFuncSetAttribute(gemm_pre<false>, cudaFuncAttributeMaxDynamicSharedMemorySize, GEMM_SMEM);
        cudaFuncSetAttribute(scores_mma, cudaFuncAttributeMaxDynamicSharedMemorySize, SCORES_SMEM);
        cudaFuncSetAttribute(pv_mma, cudaFuncAttributeMaxDynamicSharedMemorySize, PV_SMEM);
        smem_set = 1;
    }

    // split inputs + weights
    cvt_split<<<(MROWS * DD) / 1024, 256>>>(x, pXh, pXl);
    cvt_split<<<(MROWS * DD) / 1024, 256>>>(z, pZh, pZl);
    cvt_split<<<(DD * DD) / 1024, 256>>>(wq_w, pWqh, pWql);
    cvt_split<<<(DD * DD) / 1024, 256>>>(wk_w, pWkh, pWkl);
    cvt_split<<<(DD * DD) / 1024, 256>>>(wo_w, pWoh, pWol);

    const dim3 gProj(DD / 128, MROWS / 128);                 // (8,32)
    gemm_pre<false><<<gProj, 512, GEMM_SMEM>>>(pXh, pXl, pWqh, pWql, wq_b,
                                               nullptr, pQh, pQl, DD, DD);
    gemm_pre<false><<<gProj, 512, GEMM_SMEM>>>(pZh, pZl, pWkh, pWkl, wk_b,
                                               nullptr, pKh, pKl, DD, DD);

    scores_mma<<<dim3(136, BHT), 512, SCORES_SMEM>>>();

    softmax_aw<<<BB * SS, 256>>>(AW);

    pv_mma<<<dim3(16, BHT), 512, PV_SMEM>>>();

    gemm_pre<true><<<gProj, 512, GEMM_SMEM>>>(pCh, pCl, pWoh, pWol, wo_b,
                                              out, nullptr, nullptr, DD, DD);
}